// round 1
// baseline (speedup 1.0000x reference)
#include <cuda_runtime.h>

// Problem constants
#define BB 4
#define VV 256
#define HH 128
constexpr int ROWS_H = BB * VV;           // 1024
constexpr int ROWS_E = BB * VV * VV;      // 262144
constexpr int TJ     = 64;                // e-rows per block in k_main
constexpr int NBLK   = ROWS_E / TJ;       // 4096
constexpr float EPS  = 1e-5f;

// Scratch (static device arrays -- allocation-free per harness rules)
__device__ float g_enew[(size_t)ROWS_E * HH];   // 134 MB
__device__ float g_lin[4 * ROWS_H * HH];        // Uh,Vh,Ah,Bh
__device__ float g_statS[HH * NBLK];
__device__ float g_statQ[HH * NBLK];
__device__ float g_aggp[HH * NBLK];
__device__ float g_hnew[ROWS_H * HH];
__device__ float g_scaleE[HH];
__device__ float g_shiftE[HH];

// ---------- packed f32x2 helpers (Blackwell) ----------
__device__ __forceinline__ void fma2(unsigned long long& d, unsigned long long a, unsigned long long b) {
    asm("fma.rn.f32x2 %0, %1, %2, %0;" : "+l"(d) : "l"(a), "l"(b));
}
__device__ __forceinline__ float2 unpack2(unsigned long long v) {
    float2 r; asm("mov.b64 {%0,%1}, %2;" : "=f"(r.x), "=f"(r.y) : "l"(v)); return r;
}

// Shared-memory strides
constexpr int WS_STRIDE = 132;  // floats per weight row (pad: conflict-free LDS.128 across n)
// Ws:  [n][k]  natural, stride 132
// As:  [j][k]  natural, stride 128
// Inner product pairs over K via f32x2: acc holds (even-k partial, odd-k partial).

__device__ __forceinline__ void gemm_inner(const float* __restrict__ Ws,
                                           const float* __restrict__ As,
                                           int j0, int n0,
                                           unsigned long long (&acc)[8][4]) {
#pragma unroll
    for (int jl = 0; jl < 8; jl++)
#pragma unroll
        for (int nn = 0; nn < 4; nn++) acc[jl][nn] = 0ull;

#pragma unroll 2
    for (int k = 0; k < HH; k += 4) {
        ulonglong2 w0 = *(const ulonglong2*)&Ws[(n0 + 0) * WS_STRIDE + k];
        ulonglong2 w1 = *(const ulonglong2*)&Ws[(n0 + 1) * WS_STRIDE + k];
        ulonglong2 w2 = *(const ulonglong2*)&Ws[(n0 + 2) * WS_STRIDE + k];
        ulonglong2 w3 = *(const ulonglong2*)&Ws[(n0 + 3) * WS_STRIDE + k];
#pragma unroll
        for (int jl = 0; jl < 8; jl++) {
            ulonglong2 a = *(const ulonglong2*)&As[(j0 + jl) * HH + k];
            fma2(acc[jl][0], a.x, w0.x); fma2(acc[jl][0], a.y, w0.y);
            fma2(acc[jl][1], a.x, w1.x); fma2(acc[jl][1], a.y, w1.y);
            fma2(acc[jl][2], a.x, w2.x); fma2(acc[jl][2], a.y, w2.y);
            fma2(acc[jl][3], a.x, w3.x); fma2(acc[jl][3], a.y, w3.y);
        }
    }
}

// ---------------- K0: the four small linears on h ----------------
constexpr int SMEM_LIN = (HH * WS_STRIDE + TJ * HH + HH) * 4;

__global__ void k_lin(const float* __restrict__ h,
                      const float* __restrict__ W0, const float* __restrict__ b0,
                      const float* __restrict__ W1, const float* __restrict__ b1,
                      const float* __restrict__ W2, const float* __restrict__ b2,
                      const float* __restrict__ W3, const float* __restrict__ b3) {
    extern __shared__ float sm[];
    float* Ws = sm;
    float* As = Ws + HH * WS_STRIDE;
    float* bs = As + TJ * HH;

    int m = blockIdx.y;
    const float* W    = (m == 0) ? W0 : (m == 1) ? W1 : (m == 2) ? W2 : W3;
    const float* bias = (m == 0) ? b0 : (m == 1) ? b1 : (m == 2) ? b2 : b3;

    int tid = threadIdx.x;
    for (int i = tid; i < HH * 32; i += 256) {
        int n = i >> 5, kc = i & 31;
        *(float4*)&Ws[n * WS_STRIDE + kc * 4] = *(const float4*)&W[n * HH + kc * 4];
    }
    int r0 = blockIdx.x * TJ;
    const float4* hsrc = (const float4*)(h + (size_t)r0 * HH);
    for (int i = tid; i < TJ * 32; i += 256) ((float4*)As)[i] = hsrc[i];
    if (tid < 32) ((float4*)bs)[tid] = ((const float4*)bias)[tid];
    __syncthreads();

    int tr = tid >> 5, tc = tid & 31;
    int j0 = tr * 8, n0 = tc * 4;
    unsigned long long acc[8][4];
    gemm_inner(Ws, As, j0, n0, acc);

    float4 b4 = *(float4*)&bs[n0];
    float* dst = g_lin + (size_t)m * ROWS_H * HH;
#pragma unroll
    for (int jl = 0; jl < 8; jl++) {
        float2 p0 = unpack2(acc[jl][0]);
        float2 p1 = unpack2(acc[jl][1]);
        float2 p2 = unpack2(acc[jl][2]);
        float2 p3 = unpack2(acc[jl][3]);
        float4 o;
        o.x = p0.x + p0.y + b4.x;
        o.y = p1.x + p1.y + b4.y;
        o.z = p2.x + p2.y + b4.z;
        o.w = p3.x + p3.y + b4.w;
        *(float4*)&dst[(size_t)(r0 + j0 + jl) * HH + n0] = o;
    }
}

// ---------------- K1: fused Ce GEMM + e_new + gates + agg + stats ----------------
constexpr int SMEM_MAIN = (HH * WS_STRIDE + 3 * TJ * HH + 2 * HH + 3 * 8 * HH) * 4;

__global__ void k_main(const float* __restrict__ e,
                       const float* __restrict__ Cw, const float* __restrict__ Cb) {
    extern __shared__ float sm[];
    float* Ws  = sm;                       // 128*132
    float* As  = Ws + HH * WS_STRIDE;      // 64*128 (e rows)
    float* Ahs = As + TJ * HH;             // 64*128
    float* Vhs = Ahs + TJ * HH;            // 64*128
    float* Bhs = Vhs + TJ * HH;            // 128
    float* Cbs = Bhs + HH;                 // 128
    float* red = Cbs + HH;                 // 3*8*128

    int tid = threadIdx.x;
    int blk = blockIdx.x;
    int bi  = blk >> 2;           // (b*V + i)
    int jb  = blk & 3;
    int b   = bi >> 8;
    int rbase = blk * TJ;         // row base into flattened e

    // loads (all naturally laid out, fully coalesced)
    for (int i = tid; i < HH * 32; i += 256) {
        int n = i >> 5, kc = i & 31;
        *(float4*)&Ws[n * WS_STRIDE + kc * 4] = *(const float4*)&Cw[n * HH + kc * 4];
    }
    const float4* esrc = (const float4*)(e + (size_t)rbase * HH);
    const float4* ahsrc = (const float4*)(g_lin + (size_t)2 * ROWS_H * HH + (size_t)(b * VV + jb * TJ) * HH);
    const float4* vhsrc = (const float4*)(g_lin + (size_t)1 * ROWS_H * HH + (size_t)(b * VV + jb * TJ) * HH);
    for (int i = tid; i < TJ * 32; i += 256) {
        ((float4*)As)[i]  = esrc[i];
        ((float4*)Ahs)[i] = ahsrc[i];
        ((float4*)Vhs)[i] = vhsrc[i];
    }
    if (tid < 32) {
        ((float4*)Bhs)[tid] = ((const float4*)(g_lin + (size_t)3 * ROWS_H * HH + (size_t)bi * HH))[tid];
        ((float4*)Cbs)[tid] = ((const float4*)Cb)[tid];
    }
    __syncthreads();

    int tr = tid >> 5, tc = tid & 31;
    int j0 = tr * 8, n0 = tc * 4;
    unsigned long long acc[8][4];
    gemm_inner(Ws, As, j0, n0, acc);

    // epilogue: e_new, store, stats, gated aggregation
    float4 bh4 = *(float4*)&Bhs[n0];
    float4 cb4 = *(float4*)&Cbs[n0];
    float ssum[4] = {0, 0, 0, 0}, ssq[4] = {0, 0, 0, 0}, sagg[4] = {0, 0, 0, 0};
#pragma unroll
    for (int jl = 0; jl < 8; jl++) {
        int j = j0 + jl;
        float4 ah4 = *(float4*)&Ahs[j * HH + n0];
        float4 vh4 = *(float4*)&Vhs[j * HH + n0];
        float2 p0 = unpack2(acc[jl][0]);
        float2 p1 = unpack2(acc[jl][1]);
        float2 p2 = unpack2(acc[jl][2]);
        float2 p3 = unpack2(acc[jl][3]);
        float x0 = p0.x + p0.y + cb4.x + ah4.x + bh4.x;
        float x1 = p1.x + p1.y + cb4.y + ah4.y + bh4.y;
        float x2 = p2.x + p2.y + cb4.z + ah4.z + bh4.z;
        float x3 = p3.x + p3.y + cb4.w + ah4.w + bh4.w;
        float4 o; o.x = x0; o.y = x1; o.z = x2; o.w = x3;
        *(float4*)&g_enew[(size_t)(rbase + j) * HH + n0] = o;
        ssum[0] += x0; ssq[0] += x0 * x0;
        ssum[1] += x1; ssq[1] += x1 * x1;
        ssum[2] += x2; ssq[2] += x2 * x2;
        ssum[3] += x3; ssq[3] += x3 * x3;
        float g0 = 1.f / (1.f + __expf(-x0));
        float g1 = 1.f / (1.f + __expf(-x1));
        float g2 = 1.f / (1.f + __expf(-x2));
        float g3 = 1.f / (1.f + __expf(-x3));
        sagg[0] += g0 * vh4.x;
        sagg[1] += g1 * vh4.y;
        sagg[2] += g2 * vh4.z;
        sagg[3] += g3 * vh4.w;
    }
    // block-level reduction over the 8 row-groups
    *(float4*)&red[tr * HH + n0]            = make_float4(ssum[0], ssum[1], ssum[2], ssum[3]);
    *(float4*)&red[8 * HH + tr * HH + n0]   = make_float4(ssq[0], ssq[1], ssq[2], ssq[3]);
    *(float4*)&red[16 * HH + tr * HH + n0]  = make_float4(sagg[0], sagg[1], sagg[2], sagg[3]);
    __syncthreads();
    if (tid < HH) {
        float s = 0.f, q = 0.f, a = 0.f;
#pragma unroll
        for (int t = 0; t < 8; t++) {
            s += red[t * HH + tid];
            q += red[8 * HH + t * HH + tid];
            a += red[16 * HH + t * HH + tid];
        }
        g_statS[tid * NBLK + blk] = s;
        g_statQ[tid * NBLK + blk] = q;
        g_aggp[tid * NBLK + blk]  = a;   // blk == bi*4 + jb
    }
}

// ---------------- K2: stats reduce (fp64) + h path + h_out ----------------
__device__ __forceinline__ double blk_red(double v, double* sb) {
    int tid = threadIdx.x;
    sb[tid] = v; __syncthreads();
    for (int o = 128; o > 0; o >>= 1) {
        if (tid < o) sb[tid] += sb[tid + o];
        __syncthreads();
    }
    double r = sb[0]; __syncthreads();
    return r;
}

__global__ void k_finalize(const float* __restrict__ h_in,
                           const float* __restrict__ gamma_h, const float* __restrict__ beta_h,
                           const float* __restrict__ gamma_e, const float* __restrict__ beta_e,
                           float* __restrict__ out_h) {
    __shared__ double sb[256];
    __shared__ float sbroad[2];
    int n = blockIdx.x;
    int tid = threadIdx.x;

    // e-BN stats over all 262144 rows (column n)
    double s = 0.0, q = 0.0;
    for (int p = tid; p < NBLK; p += 256) {
        s += (double)g_statS[n * NBLK + p];
        q += (double)g_statQ[n * NBLK + p];
    }
    s = blk_red(s, sb);
    q = blk_red(q, sb);
    if (tid == 0) {
        double mean = s / (double)ROWS_E;
        double var  = q / (double)ROWS_E - mean * mean;
        float rstd  = (float)(1.0 / sqrt(var + (double)EPS));
        float sc    = gamma_e[n] * rstd;
        g_scaleE[n] = sc;
        g_shiftE[n] = beta_e[n] - (float)mean * sc;
    }

    // h path: agg reduce -> h_new -> BN-h stats
    double hs = 0.0, hq = 0.0;
    for (int r = tid; r < ROWS_H; r += 256) {
        const float* ap = &g_aggp[n * NBLK + r * 4];
        float agg = ap[0] + ap[1] + ap[2] + ap[3];
        float hn  = g_lin[(size_t)r * HH + n] + agg;  // Uh + agg
        g_hnew[(size_t)r * HH + n] = hn;
        hs += (double)hn; hq += (double)hn * (double)hn;
    }
    hs = blk_red(hs, sb);
    hq = blk_red(hq, sb);
    if (tid == 0) {
        double mean = hs / (double)ROWS_H;
        double var  = hq / (double)ROWS_H - mean * mean;
        float rstd  = (float)(1.0 / sqrt(var + (double)EPS));
        float sc    = gamma_h[n] * rstd;
        sbroad[0]   = sc;
        sbroad[1]   = beta_h[n] - (float)mean * sc;
    }
    __syncthreads();
    float sc = sbroad[0], sh = sbroad[1];
    for (int r = tid; r < ROWS_H; r += 256) {
        float v = fmaf(g_hnew[(size_t)r * HH + n], sc, sh);
        out_h[(size_t)r * HH + n] = h_in[(size_t)r * HH + n] + fmaxf(v, 0.f);
    }
}

// ---------------- K3: e epilogue (BN apply + relu + residual) ----------------
__global__ void k_epi(const float* __restrict__ e_in, float* __restrict__ out_e) {
    int tid = threadIdx.x;
    const float4* en4 = (const float4*)g_enew;
    const float4* ei4 = (const float4*)e_in;
    const float4* sc4 = (const float4*)g_scaleE;
    const float4* sh4 = (const float4*)g_shiftE;
    float4* out4 = (float4*)out_e;
#pragma unroll
    for (int it = 0; it < 4; it++) {
        size_t f = (size_t)blockIdx.x * 1024 + it * 256 + tid;
        int c = (int)(f & 31);
        float4 sc = __ldg(&sc4[c]);
        float4 sh = __ldg(&sh4[c]);
        float4 x  = en4[f];
        float4 ei = ei4[f];
        float4 o;
        o.x = ei.x + fmaxf(fmaf(x.x, sc.x, sh.x), 0.f);
        o.y = ei.y + fmaxf(fmaf(x.y, sc.y, sh.y), 0.f);
        o.z = ei.z + fmaxf(fmaf(x.z, sc.z, sh.z), 0.f);
        o.w = ei.w + fmaxf(fmaf(x.w, sc.w, sh.w), 0.f);
        out4[f] = o;
    }
}

extern "C" void kernel_launch(void* const* d_in, const int* in_sizes, int n_in,
                              void* d_out, int out_size) {
    (void)in_sizes; (void)n_in; (void)out_size;
    const float* h  = (const float*)d_in[0];
    const float* e  = (const float*)d_in[1];
    // d_in[2] = graph (all-ones, unused by reference math)
    const float* Uw = (const float*)d_in[3];
    const float* Ub = (const float*)d_in[4];
    const float* Vw = (const float*)d_in[5];
    const float* Vb = (const float*)d_in[6];
    const float* Aw = (const float*)d_in[7];
    const float* Ab = (const float*)d_in[8];
    const float* Bw = (const float*)d_in[9];
    const float* Bb = (const float*)d_in[10];
    const float* Cw = (const float*)d_in[11];
    const float* Cb = (const float*)d_in[12];
    const float* gh = (const float*)d_in[13];
    const float* bh = (const float*)d_in[14];
    const float* ge = (const float*)d_in[15];
    const float* be = (const float*)d_in[16];
    float* out = (float*)d_out;                 // [h_out (131072) | e_out (33554432)]

    cudaFuncSetAttribute(k_lin,  cudaFuncAttributeMaxDynamicSharedMemorySize, SMEM_LIN);
    cudaFuncSetAttribute(k_main, cudaFuncAttributeMaxDynamicSharedMemorySize, SMEM_MAIN);

    k_lin<<<dim3(ROWS_H / TJ, 4), 256, SMEM_LIN>>>(h, Uw, Ub, Vw, Vb, Aw, Ab, Bw, Bb);
    k_main<<<NBLK, 256, SMEM_MAIN>>>(e, Cw, Cb);
    k_finalize<<<HH, 256>>>(h, gh, bh, ge, be, out);
    k_epi<<<ROWS_E * HH / 4096, 256>>>(e, out + ROWS_H * HH);
}

// round 2
// speedup vs baseline: 1.5049x; 1.5049x over previous
#include <cuda_runtime.h>

// Problem constants
#define BB 4
#define VV 256
#define HH 128
constexpr int ROWS_H = BB * VV;           // 1024
constexpr int ROWS_E = BB * VV * VV;      // 262144
constexpr int TJ     = 64;                // e-rows per block in k_main
constexpr int NBLK   = ROWS_E / TJ;       // 4096
constexpr float EPS  = 1e-5f;

// Scratch (static device arrays -- allocation-free per harness rules)
__device__ float g_enew[(size_t)ROWS_E * HH];   // 134 MB
__device__ float g_lin[4 * ROWS_H * HH];        // Uh,Vh,Ah,Bh
__device__ float g_statS[HH * NBLK];
__device__ float g_statQ[HH * NBLK];
__device__ float g_aggp[HH * NBLK];
__device__ float g_hnew[ROWS_H * HH];
__device__ float g_scaleE[HH];
__device__ float g_shiftE[HH];

// ---------- packed f32x2 helpers (Blackwell) ----------
__device__ __forceinline__ void fma2(unsigned long long& d, unsigned long long a, unsigned long long b) {
    asm("fma.rn.f32x2 %0, %1, %2, %0;" : "+l"(d) : "l"(a), "l"(b));
}
__device__ __forceinline__ float2 unpack2(unsigned long long v) {
    float2 r; asm("mov.b64 {%0,%1}, %2;" : "=f"(r.x), "=f"(r.y) : "l"(v)); return r;
}

// Ws layout: [n][k], row stride 132 floats (33 16B-units, odd -> with the
// column mapping n = tc + 32m, warp-phase unit index == tc (mod 8): conflict-free).
constexpr int WS_STRIDE = 132;

// Thread mapping: tr = tid>>5 (8 warps -> 8 rows each), tc = tid&31.
// Thread computes rows j0..j0+7, columns {tc, tc+32, tc+64, tc+96}.
// acc[jl][m] is an f32x2 pair of (even-k partial, odd-k partial).
__device__ __forceinline__ void gemm_inner(const float* __restrict__ Ws,
                                           const float* __restrict__ As,
                                           int j0, int tc,
                                           unsigned long long (&acc)[8][4]) {
#pragma unroll
    for (int jl = 0; jl < 8; jl++)
#pragma unroll
        for (int m = 0; m < 4; m++) acc[jl][m] = 0ull;

#pragma unroll 4
    for (int k = 0; k < HH; k += 4) {
        ulonglong2 w0 = *(const ulonglong2*)&Ws[(tc +  0) * WS_STRIDE + k];
        ulonglong2 w1 = *(const ulonglong2*)&Ws[(tc + 32) * WS_STRIDE + k];
        ulonglong2 w2 = *(const ulonglong2*)&Ws[(tc + 64) * WS_STRIDE + k];
        ulonglong2 w3 = *(const ulonglong2*)&Ws[(tc + 96) * WS_STRIDE + k];
#pragma unroll
        for (int jl = 0; jl < 8; jl++) {
            ulonglong2 a = *(const ulonglong2*)&As[(j0 + jl) * HH + k];  // warp-uniform: broadcast
            fma2(acc[jl][0], a.x, w0.x); fma2(acc[jl][0], a.y, w0.y);
            fma2(acc[jl][1], a.x, w1.x); fma2(acc[jl][1], a.y, w1.y);
            fma2(acc[jl][2], a.x, w2.x); fma2(acc[jl][2], a.y, w2.y);
            fma2(acc[jl][3], a.x, w3.x); fma2(acc[jl][3], a.y, w3.y);
        }
    }
}

// ---------------- K0: the four small linears on h ----------------
constexpr int SMEM_LIN = (HH * WS_STRIDE + TJ * HH) * 4;

__global__ void k_lin(const float* __restrict__ h,
                      const float* __restrict__ W0, const float* __restrict__ b0,
                      const float* __restrict__ W1, const float* __restrict__ b1,
                      const float* __restrict__ W2, const float* __restrict__ b2,
                      const float* __restrict__ W3, const float* __restrict__ b3) {
    extern __shared__ float sm[];
    float* Ws = sm;
    float* As = Ws + HH * WS_STRIDE;

    int m = blockIdx.y;
    const float* W    = (m == 0) ? W0 : (m == 1) ? W1 : (m == 2) ? W2 : W3;
    const float* bias = (m == 0) ? b0 : (m == 1) ? b1 : (m == 2) ? b2 : b3;

    int tid = threadIdx.x;
    for (int i = tid; i < HH * 32; i += 256) {
        int n = i >> 5, kc = i & 31;
        *(float4*)&Ws[n * WS_STRIDE + kc * 4] = *(const float4*)&W[n * HH + kc * 4];
    }
    int r0 = blockIdx.x * TJ;
    const float4* hsrc = (const float4*)(h + (size_t)r0 * HH);
    for (int i = tid; i < TJ * 32; i += 256) ((float4*)As)[i] = hsrc[i];
    __syncthreads();

    int tr = tid >> 5, tc = tid & 31;
    int j0 = tr * 8;
    unsigned long long acc[8][4];
    gemm_inner(Ws, As, j0, tc, acc);

    float bv[4];
#pragma unroll
    for (int mm = 0; mm < 4; mm++) bv[mm] = bias[tc + 32 * mm];

    float* dst = g_lin + (size_t)m * ROWS_H * HH;
#pragma unroll
    for (int jl = 0; jl < 8; jl++) {
        size_t row = (size_t)(r0 + j0 + jl) * HH;
#pragma unroll
        for (int mm = 0; mm < 4; mm++) {
            float2 p = unpack2(acc[jl][mm]);
            dst[row + tc + 32 * mm] = p.x + p.y + bv[mm];
        }
    }
}

// ---------------- K1: fused Ce GEMM + e_new + gates + agg + stats ----------------
// smem: Ws (67.6 KB) + As (32.8 KB) ~= 100 KB -> 2 blocks/SM.
// red buffer (12 KB) aliases Ws after the GEMM.
constexpr int SMEM_MAIN = (HH * WS_STRIDE + TJ * HH) * 4;

__global__ void __launch_bounds__(256, 2)
k_main(const float* __restrict__ e,
       const float* __restrict__ Cw, const float* __restrict__ Cb) {
    extern __shared__ float sm[];
    float* Ws  = sm;                       // 128*132
    float* As  = Ws + HH * WS_STRIDE;      // 64*128 (e rows)
    float* red = sm;                       // alias (used after GEMM)

    int tid = threadIdx.x;
    int blk = blockIdx.x;
    int bi  = blk >> 2;           // (b*V + i)
    int jb  = blk & 3;
    int b   = bi >> 8;
    int rbase = blk * TJ;         // row base into flattened e

    // loads (coalesced; Ws stores stride-33-unit conflict-free)
    for (int i = tid; i < HH * 32; i += 256) {
        int n = i >> 5, kc = i & 31;
        *(float4*)&Ws[n * WS_STRIDE + kc * 4] = *(const float4*)&Cw[n * HH + kc * 4];
    }
    const float4* esrc = (const float4*)(e + (size_t)rbase * HH);
    for (int i = tid; i < TJ * 32; i += 256) ((float4*)As)[i] = esrc[i];
    __syncthreads();

    int tr = tid >> 5, tc = tid & 31;
    int j0 = tr * 8;
    unsigned long long acc[8][4];
    gemm_inner(Ws, As, j0, tc, acc);

    __syncthreads();   // everyone done reading Ws (about to alias it as 'red')

    // Per-column constants for this thread's 4 columns
    const float* bh = g_lin + (size_t)3 * ROWS_H * HH + (size_t)bi * HH;
    float bhv[4], cbv[4];
#pragma unroll
    for (int mm = 0; mm < 4; mm++) {
        bhv[mm] = bh[tc + 32 * mm];
        cbv[mm] = Cb[tc + 32 * mm];
    }

    const float* ahb = g_lin + (size_t)2 * ROWS_H * HH + (size_t)(b * VV + jb * TJ) * HH;
    const float* vhb = g_lin + (size_t)1 * ROWS_H * HH + (size_t)(b * VV + jb * TJ) * HH;

    float ssum[4] = {0, 0, 0, 0}, ssq[4] = {0, 0, 0, 0}, sagg[4] = {0, 0, 0, 0};
#pragma unroll
    for (int jl = 0; jl < 8; jl++) {
        int j = j0 + jl;
        const float* ah = ahb + (size_t)j * HH;
        const float* vh = vhb + (size_t)j * HH;
        float* dst = &g_enew[(size_t)(rbase + j) * HH];
#pragma unroll
        for (int mm = 0; mm < 4; mm++) {
            int n = tc + 32 * mm;
            float2 p = unpack2(acc[jl][mm]);
            float x = p.x + p.y + cbv[mm] + ah[n] + bhv[mm];
            dst[n] = x;
            ssum[mm] += x;
            ssq[mm]  += x * x;
            float g = 1.f / (1.f + __expf(-x));
            sagg[mm] += g * vh[n];
        }
    }

    // block-level reduction over the 8 row-groups (red aliases Ws)
#pragma unroll
    for (int mm = 0; mm < 4; mm++) {
        int n = tc + 32 * mm;
        red[tr * HH + n]           = ssum[mm];
        red[8 * HH + tr * HH + n]  = ssq[mm];
        red[16 * HH + tr * HH + n] = sagg[mm];
    }
    __syncthreads();
    if (tid < HH) {
        float s = 0.f, q = 0.f, a = 0.f;
#pragma unroll
        for (int t = 0; t < 8; t++) {
            s += red[t * HH + tid];
            q += red[8 * HH + t * HH + tid];
            a += red[16 * HH + t * HH + tid];
        }
        g_statS[tid * NBLK + blk] = s;
        g_statQ[tid * NBLK + blk] = q;
        g_aggp[tid * NBLK + blk]  = a;   // blk == bi*4 + jb
    }
}

// ---------------- K2: stats reduce (fp64) + h path + h_out ----------------
__device__ __forceinline__ double blk_red(double v, double* sb) {
    int tid = threadIdx.x;
    sb[tid] = v; __syncthreads();
    for (int o = 128; o > 0; o >>= 1) {
        if (tid < o) sb[tid] += sb[tid + o];
        __syncthreads();
    }
    double r = sb[0]; __syncthreads();
    return r;
}

__global__ void k_finalize(const float* __restrict__ h_in,
                           const float* __restrict__ gamma_h, const float* __restrict__ beta_h,
                           const float* __restrict__ gamma_e, const float* __restrict__ beta_e,
                           float* __restrict__ out_h) {
    __shared__ double sb[256];
    __shared__ float sbroad[2];
    int n = blockIdx.x;
    int tid = threadIdx.x;

    // e-BN stats over all 262144 rows (column n)
    double s = 0.0, q = 0.0;
    for (int p = tid; p < NBLK; p += 256) {
        s += (double)g_statS[n * NBLK + p];
        q += (double)g_statQ[n * NBLK + p];
    }
    s = blk_red(s, sb);
    q = blk_red(q, sb);
    if (tid == 0) {
        double mean = s / (double)ROWS_E;
        double var  = q / (double)ROWS_E - mean * mean;
        float rstd  = (float)(1.0 / sqrt(var + (double)EPS));
        float sc    = gamma_e[n] * rstd;
        g_scaleE[n] = sc;
        g_shiftE[n] = beta_e[n] - (float)mean * sc;
    }

    // h path: agg reduce -> h_new -> BN-h stats
    double hs = 0.0, hq = 0.0;
    for (int r = tid; r < ROWS_H; r += 256) {
        const float* ap = &g_aggp[n * NBLK + r * 4];
        float agg = ap[0] + ap[1] + ap[2] + ap[3];
        float hn  = g_lin[(size_t)r * HH + n] + agg;  // Uh + agg
        g_hnew[(size_t)r * HH + n] = hn;
        hs += (double)hn; hq += (double)hn * (double)hn;
    }
    hs = blk_red(hs, sb);
    hq = blk_red(hq, sb);
    if (tid == 0) {
        double mean = hs / (double)ROWS_H;
        double var  = hq / (double)ROWS_H - mean * mean;
        float rstd  = (float)(1.0 / sqrt(var + (double)EPS));
        float sc    = gamma_h[n] * rstd;
        sbroad[0]   = sc;
        sbroad[1]   = beta_h[n] - (float)mean * sc;
    }
    __syncthreads();
    float sc = sbroad[0], sh = sbroad[1];
    for (int r = tid; r < ROWS_H; r += 256) {
        float v = fmaf(g_hnew[(size_t)r * HH + n], sc, sh);
        out_h[(size_t)r * HH + n] = h_in[(size_t)r * HH + n] + fmaxf(v, 0.f);
    }
}

// ---------------- K3: e epilogue (BN apply + relu + residual) ----------------
__global__ void k_epi(const float* __restrict__ e_in, float* __restrict__ out_e) {
    int tid = threadIdx.x;
    const float4* en4 = (const float4*)g_enew;
    const float4* ei4 = (const float4*)e_in;
    const float4* sc4 = (const float4*)g_scaleE;
    const float4* sh4 = (const float4*)g_shiftE;
    float4* out4 = (float4*)out_e;
#pragma unroll
    for (int it = 0; it < 4; it++) {
        size_t f = (size_t)blockIdx.x * 1024 + it * 256 + tid;
        int c = (int)(f & 31);
        float4 sc = __ldg(&sc4[c]);
        float4 sh = __ldg(&sh4[c]);
        float4 x  = en4[f];
        float4 ei = ei4[f];
        float4 o;
        o.x = ei.x + fmaxf(fmaf(x.x, sc.x, sh.x), 0.f);
        o.y = ei.y + fmaxf(fmaf(x.y, sc.y, sh.y), 0.f);
        o.z = ei.z + fmaxf(fmaf(x.z, sc.z, sh.z), 0.f);
        o.w = ei.w + fmaxf(fmaf(x.w, sc.w, sh.w), 0.f);
        out4[f] = o;
    }
}

extern "C" void kernel_launch(void* const* d_in, const int* in_sizes, int n_in,
                              void* d_out, int out_size) {
    (void)in_sizes; (void)n_in; (void)out_size;
    const float* h  = (const float*)d_in[0];
    const float* e  = (const float*)d_in[1];
    // d_in[2] = graph (all-ones, unused by reference math)
    const float* Uw = (const float*)d_in[3];
    const float* Ub = (const float*)d_in[4];
    const float* Vw = (const float*)d_in[5];
    const float* Vb = (const float*)d_in[6];
    const float* Aw = (const float*)d_in[7];
    const float* Ab = (const float*)d_in[8];
    const float* Bw = (const float*)d_in[9];
    const float* Bb = (const float*)d_in[10];
    const float* Cw = (const float*)d_in[11];
    const float* Cb = (const float*)d_in[12];
    const float* gh = (const float*)d_in[13];
    const float* bh = (const float*)d_in[14];
    const float* ge = (const float*)d_in[15];
    const float* be = (const float*)d_in[16];
    float* out = (float*)d_out;                 // [h_out (131072) | e_out (33554432)]

    cudaFuncSetAttribute(k_lin,  cudaFuncAttributeMaxDynamicSharedMemorySize, SMEM_LIN);
    cudaFuncSetAttribute(k_main, cudaFuncAttributeMaxDynamicSharedMemorySize, SMEM_MAIN);

    k_lin<<<dim3(ROWS_H / TJ, 4), 256, SMEM_LIN>>>(h, Uw, Ub, Vw, Vb, Aw, Ab, Bw, Bb);
    k_main<<<NBLK, 256, SMEM_MAIN>>>(e, Cw, Cb);
    k_finalize<<<HH, 256>>>(h, gh, bh, ge, be, out);
    k_epi<<<ROWS_E * HH / 4096, 256>>>(e, out + ROWS_H * HH);
}